// round 1
// baseline (speedup 1.0000x reference)
#include <cuda_runtime.h>

// Problem constants
static constexpr int NB   = 4096;  // graphs
static constexpr int CN   = 62;    // nodes per graph
static constexpr int FIN  = 256;   // input features
static constexpr int HID  = 64;    // hidden width
static constexpr int TOPK = 10;

// SMEM strides (floats)
static constexpr int XS_LD = 260;  // x tile row stride (260%32=4 -> conflict-free row broadcast, %4==0 for float4)
static constexpr int HB_LD = 68;   // [64,64] buffer stride (68%32=4, %4==0)
static constexpr int XA_LD = 65;   // xa stride (odd-ish for adj-phase column reads)

// SMEM layout offsets (floats)
static constexpr int XS_OFF   = 0;                      // 64*260 = 16640  (x tile; adj logits overlay here later)
static constexpr int ADJ_OFF  = 0;                      // 64*64 = 4096 (overlay, x dead by then)
static constexpr int WB_OFF   = 16640;                  // 8192 weight staging (2 x 64x64 chunk)
static constexpr int MASK_OFF = WB_OFF + 8192;          // 24832: 64*68 = 4352 (x_mask)
static constexpr int HH_OFF   = MASK_OFF + 4352;        // 29184: 4352 (xa then h)
static constexpr int A_OFF    = HH_OFF + 4352;          // 33536: 4352 (xr / hr)
static constexpr int B_OFF    = A_OFF + 4352;           // 37888: 4352 (xroot / hroot)
static constexpr int TV_OFF   = B_OFF + 4352;           // 42240: 620 (topk values)
static constexpr int TI_OFF   = TV_OFF + 620;           // 42860: 620 (topk indices, int)
static constexpr int SMEM_FLOATS = TI_OFF + 620;        // 43480 floats = 173920 bytes

__device__ __forceinline__ float4 fma4(float s, float4 a, float4 b) {
    b.x = fmaf(s, a.x, b.x); b.y = fmaf(s, a.y, b.y);
    b.z = fmaf(s, a.z, b.z); b.w = fmaf(s, a.w, b.w);
    return b;
}

__global__ __launch_bounds__(256) void residual_graph_kernel(
    const float* __restrict__ x,
    const float* __restrict__ gate_w,  const float* __restrict__ gate_b,
    const float* __restrict__ bnlin_w, const float* __restrict__ bnlin_b,
    const float* __restrict__ rel_w1,  const float* __restrict__ rel_b1,
    const float* __restrict__ root_w1,
    const float* __restrict__ rel_w_mid, const float* __restrict__ rel_b_mid,
    const float* __restrict__ root_w_mid,
    float* __restrict__ out)
{
    extern __shared__ float sm[];
    const int b    = blockIdx.x;
    const int tid  = threadIdx.x;
    const int lane = tid & 31;
    const int wid  = tid >> 5;

    // Common tile mapping for GEMM phases: 128 threads per matrix,
    // rg in 0..15 (rows rg+16*i), cg in 0..7 (cols cg*8..cg*8+7)
    const int mtx = tid >> 7;       // which matrix of the pair
    const int t7  = tid & 127;
    const int rg  = t7 >> 3;
    const int cg  = t7 & 7;
    const int c0  = cg * 8;

    // ---------------- Phase 0: load x tile into padded SMEM ----------------
    {
        const float4* xg  = reinterpret_cast<const float4*>(x + (size_t)b * (CN * FIN));
        float4*       xs4 = reinterpret_cast<float4*>(sm + XS_OFF);
        for (int i = tid; i < CN * 64; i += 256) {
            int r = i >> 6, q = i & 63;
            xs4[r * (XS_LD / 4) + q] = xg[i];
        }
        // zero pad rows 62,63
        float4 z = make_float4(0.f, 0.f, 0.f, 0.f);
        for (int i = tid; i < 2 * 64; i += 256) {
            int r = 62 + (i >> 6), q = i & 63;
            xs4[r * (XS_LD / 4) + q] = z;
        }
    }
    __syncthreads();

    // ------- Phase 1: two passes, each = dual [62,256]x[256,64] GEMM -------
    // pass 0: gate_w  -> x_mask (tanh), bnlin_w -> xa (tanh)
    // pass 1: rel_w1  -> xr (bufA),     root_w1 -> xroot (bufB)
    for (int pass = 0; pass < 2; ++pass) {
        const float* w0 = pass ? rel_w1  : gate_w;
        const float* w1 = pass ? root_w1 : bnlin_w;

        float acc[4][8];
        #pragma unroll
        for (int i = 0; i < 4; ++i)
            #pragma unroll
            for (int q = 0; q < 8; ++q) acc[i][q] = 0.f;

        for (int ch = 0; ch < 4; ++ch) {
            // stage weight chunk [64,64] x 2 into SMEM
            {
                const float4* g0  = reinterpret_cast<const float4*>(w0 + ch * 4096);
                const float4* g1  = reinterpret_cast<const float4*>(w1 + ch * 4096);
                float4*       wb4 = reinterpret_cast<float4*>(sm + WB_OFF);
                for (int i = tid; i < 1024; i += 256) {
                    wb4[i]        = g0[i];
                    wb4[1024 + i] = g1[i];
                }
            }
            __syncthreads();
            const float* wm  = sm + WB_OFF + mtx * 4096;
            const float* xsb = sm + XS_OFF + ch * 64;
            #pragma unroll 4
            for (int kk = 0; kk < 64; ++kk) {
                float xv[4];
                #pragma unroll
                for (int i = 0; i < 4; ++i) xv[i] = xsb[(rg + 16 * i) * XS_LD + kk];
                float4 wa = *reinterpret_cast<const float4*>(wm + kk * 64 + c0);
                float4 wb = *reinterpret_cast<const float4*>(wm + kk * 64 + c0 + 4);
                float wv[8] = {wa.x, wa.y, wa.z, wa.w, wb.x, wb.y, wb.z, wb.w};
                #pragma unroll
                for (int i = 0; i < 4; ++i)
                    #pragma unroll
                    for (int q = 0; q < 8; ++q)
                        acc[i][q] = fmaf(xv[i], wv[q], acc[i][q]);
            }
            __syncthreads();
        }

        // write results
        if (pass == 0) {
            const float* bvec = mtx ? bnlin_b : gate_b;
            float bb[8];
            #pragma unroll
            for (int q = 0; q < 8; ++q) bb[q] = bvec[c0 + q];
            #pragma unroll
            for (int i = 0; i < 4; ++i) {
                int r = rg + 16 * i;
                float* dst = mtx ? (sm + HH_OFF + r * XA_LD + c0)     // xa
                                 : (sm + MASK_OFF + r * HB_LD + c0);  // x_mask
                if (r < CN) {
                    #pragma unroll
                    for (int q = 0; q < 8; ++q) dst[q] = tanhf(acc[i][q] + bb[q]);
                } else {
                    #pragma unroll
                    for (int q = 0; q < 8; ++q) dst[q] = 0.f;
                }
            }
        } else {
            #pragma unroll
            for (int i = 0; i < 4; ++i) {
                int r = rg + 16 * i;
                float* dst = (mtx ? (sm + B_OFF) : (sm + A_OFF)) + r * HB_LD + c0;
                if (r < CN) {
                    #pragma unroll
                    for (int q = 0; q < 8; ++q) dst[q] = acc[i][q];
                } else {
                    #pragma unroll
                    for (int q = 0; q < 8; ++q) dst[q] = 0.f;
                }
            }
        }
        __syncthreads();
    }

    // -------- Phase 2: adjacency logits adj[r][j] = <xa[r], xa[j]> ---------
    {
        const int rr = tid >> 3;   // rows rr, rr+32
        const int jg = tid & 7;    // cols jg*8 .. jg*8+7
        float accA[2][8];
        #pragma unroll
        for (int h2 = 0; h2 < 2; ++h2)
            #pragma unroll
            for (int q = 0; q < 8; ++q) accA[h2][q] = 0.f;

        const float* xa = sm + HH_OFF;
        for (int k = 0; k < HID; ++k) {
            float a0 = xa[rr * XA_LD + k];
            float a1 = xa[(rr + 32) * XA_LD + k];
            #pragma unroll
            for (int q = 0; q < 8; ++q) {
                float aj = xa[(jg * 8 + q) * XA_LD + k];
                accA[0][q] = fmaf(a0, aj, accA[0][q]);
                accA[1][q] = fmaf(a1, aj, accA[1][q]);
            }
        }
        float* adj = sm + ADJ_OFF;
        #pragma unroll
        for (int q = 0; q < 8; ++q) {
            int j = jg * 8 + q;
            if (j < CN) {
                if (rr < CN)      adj[rr * 64 + j]        = accA[0][q];
                if (rr + 32 < CN) adj[(rr + 32) * 64 + j] = accA[1][q];
            }
        }
    }
    __syncthreads();

    // ---------- Phase 3: softmax per row + top-10 selection ----------------
    {
        int* tix = reinterpret_cast<int*>(sm);
        for (int r = wid; r < CN; r += 8) {
            const float* arow = sm + ADJ_OFF + r * 64;
            float a0 = arow[lane];
            bool ok1 = (lane + 32) < CN;
            float a1 = ok1 ? arow[lane + 32] : -1e30f;
            float mx = fmaxf(a0, a1);
            #pragma unroll
            for (int o = 16; o; o >>= 1) mx = fmaxf(mx, __shfl_xor_sync(0xffffffffu, mx, o));
            float e0 = expf(a0 - mx);
            float e1 = ok1 ? expf(a1 - mx) : 0.f;
            float s = e0 + e1;
            #pragma unroll
            for (int o = 16; o; o >>= 1) s += __shfl_xor_sync(0xffffffffu, s, o);
            float inv = 1.f / s;
            float p0 = e0 * inv;
            float p1 = e1 * inv;
            float v0 = p0;
            float v1 = ok1 ? p1 : -1.f;
            for (int m = 0; m < TOPK; ++m) {
                float c  = fmaxf(v0, v1);
                float cm = c;
                #pragma unroll
                for (int o = 16; o; o >>= 1) cm = fmaxf(cm, __shfl_xor_sync(0xffffffffu, cm, o));
                unsigned ball = __ballot_sync(0xffffffffu, c == cm);
                int owner = __ffs(ball) - 1;
                if (lane == owner) {
                    if (v0 == cm) {
                        sm[TV_OFF + r * TOPK + m] = p0;
                        tix[TI_OFF + r * TOPK + m] = lane;
                        v0 = -1.f;
                    } else {
                        sm[TV_OFF + r * TOPK + m] = p1;
                        tix[TI_OFF + r * TOPK + m] = lane + 32;
                        v1 = -1.f;
                    }
                }
            }
        }
    }
    __syncthreads();

    // ---------- Phase 4: h1 = relu(adjS @ xr + rel_b1 + xroot) -------------
    {
        const int rr = tid >> 3;  // rows rr, rr+32
        const int jg = tid & 7;
        const int cc = jg * 8;
        float4 b4a = *reinterpret_cast<const float4*>(rel_b1 + cc);
        float4 b4b = *reinterpret_cast<const float4*>(rel_b1 + cc + 4);
        const int* tix = reinterpret_cast<const int*>(sm);
        #pragma unroll
        for (int half = 0; half < 2; ++half) {
            int r = rr + 32 * half;
            float* hdst = sm + HH_OFF + r * HB_LD + cc;
            if (r < CN) {
                float4 s0 = make_float4(0.f, 0.f, 0.f, 0.f);
                float4 s1 = make_float4(0.f, 0.f, 0.f, 0.f);
                #pragma unroll
                for (int m = 0; m < TOPK; ++m) {
                    int   j = tix[TI_OFF + r * TOPK + m];
                    float v = sm[TV_OFF + r * TOPK + m];
                    const float4* src = reinterpret_cast<const float4*>(sm + A_OFF + j * HB_LD + cc);
                    s0 = fma4(v, src[0], s0);
                    s1 = fma4(v, src[1], s1);
                }
                const float4* rt = reinterpret_cast<const float4*>(sm + B_OFF + r * HB_LD + cc);
                float4 r0 = rt[0], r1 = rt[1];
                hdst[0] = fmaxf(s0.x + b4a.x + r0.x, 0.f);
                hdst[1] = fmaxf(s0.y + b4a.y + r0.y, 0.f);
                hdst[2] = fmaxf(s0.z + b4a.z + r0.z, 0.f);
                hdst[3] = fmaxf(s0.w + b4a.w + r0.w, 0.f);
                hdst[4] = fmaxf(s1.x + b4b.x + r1.x, 0.f);
                hdst[5] = fmaxf(s1.y + b4b.y + r1.y, 0.f);
                hdst[6] = fmaxf(s1.z + b4b.z + r1.z, 0.f);
                hdst[7] = fmaxf(s1.w + b4b.w + r1.w, 0.f);
            } else {
                #pragma unroll
                for (int q = 0; q < 8; ++q) hdst[q] = 0.f;
            }
        }
    }
    __syncthreads();

    // ---------------- Phase 5: six graph-conv layers -----------------------
    for (int L = 0; L < 6; ++L) {
        // stage mid weights [64,64] x 2
        {
            const float4* g0  = reinterpret_cast<const float4*>(rel_w_mid + L * 4096);
            const float4* g1  = reinterpret_cast<const float4*>(root_w_mid + L * 4096);
            float4*       wb4 = reinterpret_cast<float4*>(sm + WB_OFF);
            for (int i = tid; i < 1024; i += 256) {
                wb4[i]        = g0[i];
                wb4[1024 + i] = g1[i];
            }
        }
        __syncthreads();

        // hr = h @ rel_w (mtx 0 -> bufA), hroot = h @ root_w (mtx 1 -> bufB)
        {
            float acc[4][8];
            #pragma unroll
            for (int i = 0; i < 4; ++i)
                #pragma unroll
                for (int q = 0; q < 8; ++q) acc[i][q] = 0.f;
            const float* wm = sm + WB_OFF + mtx * 4096;
            const float* hb = sm + HH_OFF;
            #pragma unroll 4
            for (int k = 0; k < HID; ++k) {
                float xv[4];
                #pragma unroll
                for (int i = 0; i < 4; ++i) xv[i] = hb[(rg + 16 * i) * HB_LD + k];
                float4 wa = *reinterpret_cast<const float4*>(wm + k * 64 + c0);
                float4 wb = *reinterpret_cast<const float4*>(wm + k * 64 + c0 + 4);
                float wv[8] = {wa.x, wa.y, wa.z, wa.w, wb.x, wb.y, wb.z, wb.w};
                #pragma unroll
                for (int i = 0; i < 4; ++i)
                    #pragma unroll
                    for (int q = 0; q < 8; ++q)
                        acc[i][q] = fmaf(xv[i], wv[q], acc[i][q]);
            }
            float* dstbase = mtx ? (sm + B_OFF) : (sm + A_OFF);
            #pragma unroll
            for (int i = 0; i < 4; ++i) {
                int r = rg + 16 * i;
                if (r < CN) {
                    float* dst = dstbase + r * HB_LD + c0;
                    #pragma unroll
                    for (int q = 0; q < 8; ++q) dst[q] = acc[i][q];
                }
            }
        }
        __syncthreads();

        // h update: t = relu(adjS @ hr + rel_b_mid[L] + hroot); h = (L<5) ? h+t : t
        {
            const int rr = tid >> 3;
            const int jg = tid & 7;
            const int cc = jg * 8;
            const float* relb = rel_b_mid + L * 64;
            float4 b4a = *reinterpret_cast<const float4*>(relb + cc);
            float4 b4b = *reinterpret_cast<const float4*>(relb + cc + 4);
            const int* tix = reinterpret_cast<const int*>(sm);
            #pragma unroll
            for (int half = 0; half < 2; ++half) {
                int r = rr + 32 * half;
                if (r >= CN) continue;
                float* hdst = sm + HH_OFF + r * HB_LD + cc;
                float4 s0 = make_float4(0.f, 0.f, 0.f, 0.f);
                float4 s1 = make_float4(0.f, 0.f, 0.f, 0.f);
                #pragma unroll
                for (int m = 0; m < TOPK; ++m) {
                    int   j = tix[TI_OFF + r * TOPK + m];
                    float v = sm[TV_OFF + r * TOPK + m];
                    const float4* src = reinterpret_cast<const float4*>(sm + A_OFF + j * HB_LD + cc);
                    s0 = fma4(v, src[0], s0);
                    s1 = fma4(v, src[1], s1);
                }
                const float4* rt = reinterpret_cast<const float4*>(sm + B_OFF + r * HB_LD + cc);
                float4 r0 = rt[0], r1 = rt[1];
                float t0 = fmaxf(s0.x + b4a.x + r0.x, 0.f);
                float t1 = fmaxf(s0.y + b4a.y + r0.y, 0.f);
                float t2 = fmaxf(s0.z + b4a.z + r0.z, 0.f);
                float t3 = fmaxf(s0.w + b4a.w + r0.w, 0.f);
                float t4 = fmaxf(s1.x + b4b.x + r1.x, 0.f);
                float t5 = fmaxf(s1.y + b4b.y + r1.y, 0.f);
                float t6 = fmaxf(s1.z + b4b.z + r1.z, 0.f);
                float t7v = fmaxf(s1.w + b4b.w + r1.w, 0.f);
                if (L < 5) {
                    hdst[0] += t0; hdst[1] += t1; hdst[2] += t2; hdst[3] += t3;
                    hdst[4] += t4; hdst[5] += t5; hdst[6] += t6; hdst[7] += t7v;
                } else {
                    hdst[0] = t0; hdst[1] = t1; hdst[2] = t2; hdst[3] = t3;
                    hdst[4] = t4; hdst[5] = t5; hdst[6] = t6; hdst[7] = t7v;
                }
            }
        }
        __syncthreads();
    }

    // ---------------- Phase 6: out = h * x_mask ----------------------------
    {
        const int rr = tid >> 3;
        const int jg = tid & 7;
        const int cc = jg * 8;
        #pragma unroll
        for (int half = 0; half < 2; ++half) {
            int r = rr + 32 * half;
            if (r >= CN) continue;
            const float4* hp = reinterpret_cast<const float4*>(sm + HH_OFF + r * HB_LD + cc);
            const float4* mp = reinterpret_cast<const float4*>(sm + MASK_OFF + r * HB_LD + cc);
            float4 h0 = hp[0], h1 = hp[1];
            float4 m0 = mp[0], m1 = mp[1];
            float4 o0, o1;
            o0.x = h0.x * m0.x; o0.y = h0.y * m0.y; o0.z = h0.z * m0.z; o0.w = h0.w * m0.w;
            o1.x = h1.x * m1.x; o1.y = h1.y * m1.y; o1.z = h1.z * m1.z; o1.w = h1.w * m1.w;
            float4* og = reinterpret_cast<float4*>(out + (size_t)b * (CN * HID) + r * HID + cc);
            og[0] = o0;
            og[1] = o1;
        }
    }
}

extern "C" void kernel_launch(void* const* d_in, const int* in_sizes, int n_in,
                              void* d_out, int out_size) {
    const float* x          = (const float*)d_in[0];
    const float* gate_w     = (const float*)d_in[1];
    const float* gate_b     = (const float*)d_in[2];
    const float* bnlin_w    = (const float*)d_in[3];
    const float* bnlin_b    = (const float*)d_in[4];
    const float* rel_w1     = (const float*)d_in[5];
    const float* rel_b1     = (const float*)d_in[6];
    const float* root_w1    = (const float*)d_in[7];
    const float* rel_w_mid  = (const float*)d_in[8];
    const float* rel_b_mid  = (const float*)d_in[9];
    const float* root_w_mid = (const float*)d_in[10];
    float* out = (float*)d_out;

    (void)in_sizes; (void)n_in; (void)out_size;

    const int smem_bytes = SMEM_FLOATS * 4;
    cudaFuncSetAttribute(residual_graph_kernel,
                         cudaFuncAttributeMaxDynamicSharedMemorySize, smem_bytes);
    residual_graph_kernel<<<NB, 256, smem_bytes>>>(
        x, gate_w, gate_b, bnlin_w, bnlin_b, rel_w1, rel_b1, root_w1,
        rel_w_mid, rel_b_mid, root_w_mid, out);
}